// round 9
// baseline (speedup 1.0000x reference)
#include <cuda_runtime.h>
#include <cstdint>
#include <cstddef>

// Problem constants
#define B_   4
#define C_   192
#define H_   128
#define W_   128
#define P_   16384
#define ND   3
#define C2   64
#define NH   2
#define HD   32
#define MQKV 576
#define SCALE 0.17677669529663687f   // 32^-0.5

// Scratch (alloc-free: __device__ globals)
__device__ float g_x  [(size_t)B_*C_*P_];
__device__ float g_qkv[(size_t)B_*MQKV*P_];
__device__ float g_xo [(size_t)B_*C_*P_];

// ---------------------------------------------------------------------------
// Stage 1: depthwise 3x3 conv (zero pad) + residual + bias
// ---------------------------------------------------------------------------
__global__ __launch_bounds__(256) void pos_kernel(
    const float* __restrict__ x, const float* __restrict__ pw,
    const float* __restrict__ pb)
{
    int idx = blockIdx.x * 256 + threadIdx.x;
    if (idx >= B_*C_*P_) return;
    int pix = idx & (P_-1);
    int bc  = idx >> 14;
    int c   = bc % C_;
    int y  = pix >> 7;
    int xx = pix & 127;
    const float* xb = x + (size_t)bc * P_;
    const float* w  = pw + c * 9;
    float s = x[idx];
    #pragma unroll
    for (int kh = 0; kh < 3; kh++) {
        int yy = y + kh - 1;
        if (yy < 0 || yy >= H_) continue;
        #pragma unroll
        for (int kw = 0; kw < 3; kw++) {
            int xc = xx + kw - 1;
            if (xc < 0 || xc >= W_) continue;
            s += xb[yy * W_ + xc] * w[kh * 3 + kw];
        }
    }
    g_x[idx] = s + pb[c];
}

// ---------------------------------------------------------------------------
// tf32 mma.sync GEMM:  Y[b, m, p] = sum_c Wm[m, c] * X[b, c, p]
// Block = one 128-pixel tile for one batch; full-K X tile resident in SMEM.
// 256 threads = 8 warps (2m x 4n), warp tile 32x32 via m16n8k8 tf32 HMMA.
// Pipelined: W for iter i+1 prefetched into REGISTERS during iter i's
// mainloop; As double-buffered; epilogue stores directly from fragments.
// -> exactly ONE __syncthreads per m-iteration.
// ---------------------------------------------------------------------------
#define GBM 64
#define GBN 128
#define GK  192
#define NKS 24             // k-steps of 8
#define KP2 200            // A row stride (pair-permuted (k,k+4) interleave)
#define BNP 136            // B row pad: (8*lc + lr) banks all distinct
#define AS0_OFF 26112                          // Bs: 192*136 floats
#define AS1_OFF (AS0_OFF + GBM * KP2)          // + As0 12800 floats
#define SM_FLOATS (AS1_OFF + GBM * KP2)        // + As1 -> 51712 floats
#define SM_BYTES  (SM_FLOATS * 4)              // 206848 bytes

__device__ __forceinline__ float f2tf(float f) {
    uint32_t u;
    asm("cvt.rna.tf32.f32 %0, %1;" : "=r"(u) : "f"(f));
    return __uint_as_float(u);
}

__device__ __forceinline__ void mma_tf32(float (&d)[4], const uint32_t (&a)[4],
                                         const uint32_t (&b)[2]) {
    asm volatile(
        "mma.sync.aligned.m16n8k8.row.col.f32.tf32.tf32.f32 "
        "{%0,%1,%2,%3}, {%4,%5,%6,%7}, {%8,%9}, {%0,%1,%2,%3};"
        : "+f"(d[0]), "+f"(d[1]), "+f"(d[2]), "+f"(d[3])
        : "r"(a[0]), "r"(a[1]), "r"(a[2]), "r"(a[3]), "r"(b[0]), "r"(b[1]));
}

__global__ __launch_bounds__(256, 1) void gemm_mma(
    const float* __restrict__ Wm, const float* __restrict__ X,
    float* __restrict__ Y, int Mtot)
{
    extern __shared__ float sm[];
    float* Bs = sm;                 // [GK][BNP] k-major
    float* AsBuf[2] = { sm + AS0_OFF, sm + AS1_OFF };   // pair-permuted W tiles
    const uint32_t* Bsu = reinterpret_cast<const uint32_t*>(Bs);

    int tid  = threadIdx.x;
    int lane = tid & 31;
    int wid  = tid >> 5;
    int wm   = wid & 1;             // 2 warps along m
    int wn   = wid >> 1;            // 4 warps along n
    int b    = blockIdx.y;
    int n0   = blockIdx.x * GBN;
    const float* Xb = X + (size_t)b * C_ * P_;
    float* Yb = Y + (size_t)b * Mtot * P_;
    int niter = Mtot / GBM;

    // W chunk mapping (fixed across iters): 6 chunks of 8 k per thread
    int crow[6], cs[6];
    #pragma unroll
    for (int i = 0; i < 6; i++) {
        int idx = tid + i * 256;        // 1536 chunks = 64 rows x 24 s
        crow[i] = idx / NKS;
        cs[i]   = idx - crow[i] * NKS;
    }

    // Fill Bs once: X[k][n0..n0+127] as tf32 bits. 6144 float4s / 256 = 24 each.
    #pragma unroll
    for (int i = 0; i < 24; i++) {
        int idx = tid + i * 256;
        int row = idx >> 5;
        int c4  = (idx & 31) << 2;
        float4 v = *reinterpret_cast<const float4*>(Xb + (size_t)row * P_ + n0 + c4);
        float4 t;
        t.x = f2tf(v.x); t.y = f2tf(v.y); t.z = f2tf(v.z); t.w = f2tf(v.w);
        *reinterpret_cast<float4*>(Bs + row * BNP + c4) = t;
    }

    // Prologue: load W(m0=0) into regs, stage into As[0]
    float4 wreg[12];
    #pragma unroll
    for (int i = 0; i < 6; i++) {
        const float* wp = Wm + (size_t)crow[i] * GK + cs[i] * 8;
        wreg[2*i]   = *reinterpret_cast<const float4*>(wp);
        wreg[2*i+1] = *reinterpret_cast<const float4*>(wp + 4);
    }
    #pragma unroll
    for (int i = 0; i < 6; i++) {
        float* dst = AsBuf[0] + crow[i] * KP2 + cs[i] * 8;
        float2 p;
        p.x = f2tf(wreg[2*i].x); p.y = f2tf(wreg[2*i+1].x);
        *reinterpret_cast<float2*>(dst)     = p;
        p.x = f2tf(wreg[2*i].y); p.y = f2tf(wreg[2*i+1].y);
        *reinterpret_cast<float2*>(dst + 2) = p;
        p.x = f2tf(wreg[2*i].z); p.y = f2tf(wreg[2*i+1].z);
        *reinterpret_cast<float2*>(dst + 4) = p;
        p.x = f2tf(wreg[2*i].w); p.y = f2tf(wreg[2*i+1].w);
        *reinterpret_cast<float2*>(dst + 6) = p;
    }
    __syncthreads();

    // Prefetch W(m0=GBM) into regs (hidden under first mainloop)
    if (niter > 1) {
        const float* Wn = Wm + (size_t)GBM * GK;
        #pragma unroll
        for (int i = 0; i < 6; i++) {
            const float* wp = Wn + (size_t)crow[i] * GK + cs[i] * 8;
            wreg[2*i]   = *reinterpret_cast<const float4*>(wp);
            wreg[2*i+1] = *reinterpret_cast<const float4*>(wp + 4);
        }
    }

    int lr = lane >> 2;   // 0..7
    int lc = lane & 3;    // 0..3

    for (int it = 0; it < niter; it++) {
        const float* As = AsBuf[it & 1];
        int m0 = it * GBM;

        float acc[2][4][4];
        #pragma unroll
        for (int mt = 0; mt < 2; mt++)
            #pragma unroll
            for (int nt = 0; nt < 4; nt++)
                #pragma unroll
                for (int r = 0; r < 4; r++) acc[mt][nt][r] = 0.f;

        #pragma unroll
        for (int s = 0; s < NKS; s++) {
            int k = s * 8;
            uint32_t a[2][4], bf[4][2];
            #pragma unroll
            for (int mt = 0; mt < 2; mt++) {
                int r = wm * 32 + mt * 16 + lr;
                uint2 u0 = *reinterpret_cast<const uint2*>(As + r * KP2 + k + 2 * lc);
                uint2 u1 = *reinterpret_cast<const uint2*>(As + (r + 8) * KP2 + k + 2 * lc);
                a[mt][0] = u0.x; a[mt][2] = u0.y;
                a[mt][1] = u1.x; a[mt][3] = u1.y;
            }
            #pragma unroll
            for (int nt = 0; nt < 4; nt++) {
                int c0 = (k + lc) * BNP + wn * 32 + nt * 8 + lr;
                bf[nt][0] = Bsu[c0];
                bf[nt][1] = Bsu[c0 + 4 * BNP];
            }
            #pragma unroll
            for (int mt = 0; mt < 2; mt++)
                #pragma unroll
                for (int nt = 0; nt < 4; nt++)
                    mma_tf32(acc[mt][nt], a[mt], bf[nt]);
        }

        // Stage next W tile from regs into the other As buffer
        if (it + 1 < niter) {
            float* dstb = AsBuf[(it + 1) & 1];
            #pragma unroll
            for (int i = 0; i < 6; i++) {
                float* dst = dstb + crow[i] * KP2 + cs[i] * 8;
                float2 p;
                p.x = f2tf(wreg[2*i].x); p.y = f2tf(wreg[2*i+1].x);
                *reinterpret_cast<float2*>(dst)     = p;
                p.x = f2tf(wreg[2*i].y); p.y = f2tf(wreg[2*i+1].y);
                *reinterpret_cast<float2*>(dst + 2) = p;
                p.x = f2tf(wreg[2*i].z); p.y = f2tf(wreg[2*i+1].z);
                *reinterpret_cast<float2*>(dst + 4) = p;
                p.x = f2tf(wreg[2*i].w); p.y = f2tf(wreg[2*i+1].w);
                *reinterpret_cast<float2*>(dst + 6) = p;
            }
        }

        // Epilogue: direct float2 stores from fragments (sector-aligned)
        #pragma unroll
        for (int mt = 0; mt < 2; mt++)
            #pragma unroll
            for (int nt = 0; nt < 4; nt++) {
                int r = m0 + wm * 32 + mt * 16 + lr;
                int c = n0 + wn * 32 + nt * 8 + lc * 2;
                float2 v0 = { acc[mt][nt][0], acc[mt][nt][1] };
                float2 v1 = { acc[mt][nt][2], acc[mt][nt][3] };
                *reinterpret_cast<float2*>(Yb + (size_t)r * P_ + c)       = v0;
                *reinterpret_cast<float2*>(Yb + (size_t)(r + 8) * P_ + c) = v1;
            }

        __syncthreads();   // As[(it+1)&1] visible; As[it&1] safe to overwrite next iter

        // Prefetch W for iter it+2 (hidden under iter it+1's mainloop)
        if (it + 2 < niter) {
            const float* Wn = Wm + (size_t)(it + 2) * GBM * GK;
            #pragma unroll
            for (int i = 0; i < 6; i++) {
                const float* wp = Wn + (size_t)crow[i] * GK + cs[i] * 8;
                wreg[2*i]   = *reinterpret_cast<const float4*>(wp);
                wreg[2*i+1] = *reinterpret_cast<const float4*>(wp + 4);
            }
        }
    }
}

// ---------------------------------------------------------------------------
// Stage 3: multi-dilate window attention
// ---------------------------------------------------------------------------
__device__ __forceinline__ int reflect_i(int t, int n) {
    return t < 0 ? -t : (t >= n ? 2*n - 2 - t : t);
}

__global__ __launch_bounds__(256) void attn_kernel()
{
    int p    = blockIdx.x * 256 + threadIdx.x;
    int head = blockIdx.y & 1;
    int dil  = blockIdx.y >> 1;
    int b    = blockIdx.z;
    int dl   = dil + 1;

    int y  = p >> 7;
    int xx = p & 127;

    int nb[9];
    #pragma unroll
    for (int jy = 0; jy < 3; jy++) {
        int yy = reflect_i(y + (jy-1)*dl, H_);
        #pragma unroll
        for (int jx = 0; jx < 3; jx++) {
            int xc = reflect_i(xx + (jx-1)*dl, W_);
            nb[jy*3 + jx] = yy * W_ + xc;
        }
    }

    size_t chan0 = (size_t)b * MQKV + dil * C2 + head * HD;
    const float* qp = g_qkv + chan0 * P_;
    const float* kp = g_qkv + (chan0 + (size_t)C_)   * P_;
    const float* vp = g_qkv + (chan0 + (size_t)2*C_) * P_;

    float sc[9];
    #pragma unroll
    for (int j = 0; j < 9; j++) sc[j] = 0.f;

    #pragma unroll 4
    for (int d = 0; d < HD; d++) {
        float qd = qp[(size_t)d * P_ + p];
        const float* kr = kp + (size_t)d * P_;
        #pragma unroll
        for (int j = 0; j < 9; j++) sc[j] += qd * kr[nb[j]];
    }

    float mx = sc[0] * SCALE;
    #pragma unroll
    for (int j = 0; j < 9; j++) { sc[j] *= SCALE; mx = fmaxf(mx, sc[j]); }
    float sum = 0.f;
    #pragma unroll
    for (int j = 0; j < 9; j++) { sc[j] = __expf(sc[j] - mx); sum += sc[j]; }
    float inv = 1.f / sum;

    float* op = g_xo + ((size_t)b * C_ + dil * C2 + head * HD) * P_ + p;
    #pragma unroll 4
    for (int d = 0; d < HD; d++) {
        const float* vr = vp + (size_t)d * P_;
        float a = 0.f;
        #pragma unroll
        for (int j = 0; j < 9; j++) a += sc[j] * vr[nb[j]];
        op[(size_t)d * P_] = a * inv;
    }
}

// ---------------------------------------------------------------------------
extern "C" void kernel_launch(void* const* d_in, const int* in_sizes, int n_in,
                              void* d_out, int out_size)
{
    const float* x      = (const float*)d_in[0];
    const float* pos_w  = (const float*)d_in[1];
    const float* pos_b  = (const float*)d_in[2];
    const float* qkv_w  = (const float*)d_in[3];
    const float* proj_w = (const float*)d_in[4];
    float* out = (float*)d_out;

    float *gx, *gq, *go;
    cudaGetSymbolAddress((void**)&gx, g_x);
    cudaGetSymbolAddress((void**)&gq, g_qkv);
    cudaGetSymbolAddress((void**)&go, g_xo);

    cudaFuncSetAttribute(gemm_mma, cudaFuncAttributeMaxDynamicSharedMemorySize, SM_BYTES);

    // Stage 1: positional dwconv + residual + bias
    {
        int total = B_*C_*P_;
        pos_kernel<<<(total + 255)/256, 256>>>(x, pos_w, pos_b);
    }
    // Stage 2: qkv 1x1 conv (576 x 192 x 16384 per batch)
    {
        dim3 grid(P_/GBN, B_);
        gemm_mma<<<grid, 256, SM_BYTES>>>(qkv_w, gx, gq, MQKV);
    }
    // Stage 3: attention
    {
        dim3 grid(P_/256, NH*ND, B_);
        attn_kernel<<<grid, 256>>>();
    }
    // Stage 4: projection (192 x 192 x 16384 per batch)
    {
        dim3 grid(P_/GBN, B_);
        gemm_mma<<<grid, 256, SM_BYTES>>>(proj_w, go, out, C_);
    }
}

// round 10
// speedup vs baseline: 1.0338x; 1.0338x over previous
#include <cuda_runtime.h>
#include <cstdint>
#include <cstddef>

// Problem constants
#define B_   4
#define C_   192
#define H_   128
#define W_   128
#define P_   16384
#define ND   3
#define C2   64
#define NH   2
#define HD   32
#define MQKV 576
#define SCALE 0.17677669529663687f   // 32^-0.5

// Scratch (alloc-free: __device__ globals)
__device__ float g_x  [(size_t)B_*C_*P_];
__device__ float g_qkv[(size_t)B_*MQKV*P_];
__device__ float g_xo [(size_t)B_*C_*P_];

// ---------------------------------------------------------------------------
// Stage 1: depthwise 3x3 conv (zero pad) + residual + bias
// ---------------------------------------------------------------------------
__global__ __launch_bounds__(256) void pos_kernel(
    const float* __restrict__ x, const float* __restrict__ pw,
    const float* __restrict__ pb)
{
    int idx = blockIdx.x * 256 + threadIdx.x;
    if (idx >= B_*C_*P_) return;
    int pix = idx & (P_-1);
    int bc  = idx >> 14;
    int c   = bc % C_;
    int y  = pix >> 7;
    int xx = pix & 127;
    const float* xb = x + (size_t)bc * P_;
    const float* w  = pw + c * 9;
    float s = x[idx];
    #pragma unroll
    for (int kh = 0; kh < 3; kh++) {
        int yy = y + kh - 1;
        if (yy < 0 || yy >= H_) continue;
        #pragma unroll
        for (int kw = 0; kw < 3; kw++) {
            int xc = xx + kw - 1;
            if (xc < 0 || xc >= W_) continue;
            s += xb[yy * W_ + xc] * w[kh * 3 + kw];
        }
    }
    g_x[idx] = s + pb[c];
}

// ---------------------------------------------------------------------------
// tf32 mma.sync GEMM:  Y[b, m, p] = sum_c Wm[m, c] * X[b, c, p]
// Classic k-tiled, double-buffered, SMALL smem (29.7 KB) -> 2 CTAs/SM.
// CTA tile 64(m) x 128(n) x 16(k); 8 warps (2m x 4n); warp tile 32x32.
// A pair-permuted (k,k+4) so fragment loads are LDS.64 (AP=24: 8 mod 32).
// X re-reads across m-tiles hit L2 (12.6 MB/batch << 126 MB L2).
// ---------------------------------------------------------------------------
#define GBM 64
#define GBN 128
#define GK  192
#define BKT 16              // k-tile (2 mma k-steps)
#define NKT 12              // 192/16
#define AP  24              // As row stride (words), 24 mod 32 = 24; frag-safe
#define BNP 136             // Bs row stride: 8 mod 32 -> conflict-free frags
#define AS_WORDS (GBM * AP)     // 1536
#define BS_WORDS (BKT * BNP)    // 2176

__device__ __forceinline__ float f2tf(float f) {
    uint32_t u;
    asm("cvt.rna.tf32.f32 %0, %1;" : "=r"(u) : "f"(f));
    return __uint_as_float(u);
}

__device__ __forceinline__ void mma_tf32(float (&d)[4], const uint32_t (&a)[4],
                                         const uint32_t (&b)[2]) {
    asm volatile(
        "mma.sync.aligned.m16n8k8.row.col.f32.tf32.tf32.f32 "
        "{%0,%1,%2,%3}, {%4,%5,%6,%7}, {%8,%9}, {%0,%1,%2,%3};"
        : "+f"(d[0]), "+f"(d[1]), "+f"(d[2]), "+f"(d[3])
        : "r"(a[0]), "r"(a[1]), "r"(a[2]), "r"(a[3]), "r"(b[0]), "r"(b[1]));
}

__global__ __launch_bounds__(256, 2) void gemm_mma(
    const float* __restrict__ Wm, const float* __restrict__ X,
    float* __restrict__ Y, int Mtot)
{
    __shared__ float As[2][AS_WORDS];
    __shared__ float Bs[2][BS_WORDS];

    int tid  = threadIdx.x;
    int lane = tid & 31;
    int wid  = tid >> 5;
    int wm   = wid & 1;             // 2 warps along m
    int wn   = wid >> 1;            // 4 warps along n
    int n0   = blockIdx.x * GBN;
    int m0   = blockIdx.y * GBM;
    int b    = blockIdx.z;
    const float* Xb = X + (size_t)b * C_ * P_;
    float* Yb = Y + (size_t)b * Mtot * P_;

    // --- fill mappings (fixed per thread) ---
    // As: 64 rows x 16 k = 1024 floats; 1 float4/thread.
    int arow = tid >> 2;
    int ak4  = (tid & 3) << 2;           // 0,4,8,12
    int as_  = (tid >> 1) & 1;           // kstep of this float4
    int ahi  = tid & 1;                  // (k&4)>>2
    int abase = arow * AP + as_ * 8 + ahi;
    const float* aptr = Wm + (size_t)(m0 + arow) * GK + ak4;
    // Bs: 16 rows x 128 n = 2048 floats; 2 float4/thread.
    int brow0 = tid >> 5;                // idx = tid
    int bc40  = (tid & 31) << 2;
    int brow1 = (tid + 256) >> 5;
    int bc41  = bc40;                    // (idx&31) identical for +256
    const float* bptr0 = Xb + (size_t)brow0 * P_ + n0 + bc40;
    const float* bptr1 = Xb + (size_t)brow1 * P_ + n0 + bc41;
    int bs_off0 = brow0 * BNP + bc40;
    int bs_off1 = brow1 * BNP + bc41;

    float4 aw, bw0, bw1;

    // prologue: tile 0 -> smem buf 0
    aw  = *reinterpret_cast<const float4*>(aptr);
    bw0 = *reinterpret_cast<const float4*>(bptr0);
    bw1 = *reinterpret_cast<const float4*>(bptr1);
    {
        float* d = &As[0][abase];
        d[0] = f2tf(aw.x); d[2] = f2tf(aw.y); d[4] = f2tf(aw.z); d[6] = f2tf(aw.w);
        float4 t;
        t.x = f2tf(bw0.x); t.y = f2tf(bw0.y); t.z = f2tf(bw0.z); t.w = f2tf(bw0.w);
        *reinterpret_cast<float4*>(&Bs[0][bs_off0]) = t;
        t.x = f2tf(bw1.x); t.y = f2tf(bw1.y); t.z = f2tf(bw1.z); t.w = f2tf(bw1.w);
        *reinterpret_cast<float4*>(&Bs[0][bs_off1]) = t;
    }
    __syncthreads();
    // prefetch tile 1 into regs
    aw  = *reinterpret_cast<const float4*>(aptr + BKT);
    bw0 = *reinterpret_cast<const float4*>(bptr0 + (size_t)BKT * P_);
    bw1 = *reinterpret_cast<const float4*>(bptr1 + (size_t)BKT * P_);

    float acc[2][4][4];
    #pragma unroll
    for (int mt = 0; mt < 2; mt++)
        #pragma unroll
        for (int nt = 0; nt < 4; nt++)
            #pragma unroll
            for (int r = 0; r < 4; r++) acc[mt][nt][r] = 0.f;

    int lr = lane >> 2;
    int lc = lane & 3;

    for (int t = 0; t < NKT; t++) {
        const float* Asb = As[t & 1];
        const uint32_t* Bsu = reinterpret_cast<const uint32_t*>(Bs[t & 1]);

        #pragma unroll
        for (int s = 0; s < 2; s++) {
            uint32_t a[2][4], bf[4][2];
            #pragma unroll
            for (int mt = 0; mt < 2; mt++) {
                int r = wm * 32 + mt * 16 + lr;
                uint2 u0 = *reinterpret_cast<const uint2*>(Asb + r * AP + s * 8 + 2 * lc);
                uint2 u1 = *reinterpret_cast<const uint2*>(Asb + (r + 8) * AP + s * 8 + 2 * lc);
                a[mt][0] = u0.x; a[mt][2] = u0.y;
                a[mt][1] = u1.x; a[mt][3] = u1.y;
            }
            #pragma unroll
            for (int nt = 0; nt < 4; nt++) {
                int c0 = (s * 8 + lc) * BNP + wn * 32 + nt * 8 + lr;
                bf[nt][0] = Bsu[c0];
                bf[nt][1] = Bsu[c0 + 4 * BNP];
            }
            #pragma unroll
            for (int mt = 0; mt < 2; mt++)
                #pragma unroll
                for (int nt = 0; nt < 4; nt++)
                    mma_tf32(acc[mt][nt], a[mt], bf[nt]);
        }

        if (t + 1 < NKT) {
            // stage prefetched tile t+1 into the other buffer
            float* d = &As[(t + 1) & 1][abase];
            d[0] = f2tf(aw.x); d[2] = f2tf(aw.y); d[4] = f2tf(aw.z); d[6] = f2tf(aw.w);
            float4 tv;
            tv.x = f2tf(bw0.x); tv.y = f2tf(bw0.y); tv.z = f2tf(bw0.z); tv.w = f2tf(bw0.w);
            *reinterpret_cast<float4*>(&Bs[(t + 1) & 1][bs_off0]) = tv;
            tv.x = f2tf(bw1.x); tv.y = f2tf(bw1.y); tv.z = f2tf(bw1.z); tv.w = f2tf(bw1.w);
            *reinterpret_cast<float4*>(&Bs[(t + 1) & 1][bs_off1]) = tv;
        }
        __syncthreads();
        if (t + 2 < NKT) {
            int k0 = (t + 2) * BKT;
            aw  = *reinterpret_cast<const float4*>(aptr + k0);
            bw0 = *reinterpret_cast<const float4*>(bptr0 + (size_t)k0 * P_);
            bw1 = *reinterpret_cast<const float4*>(bptr1 + (size_t)k0 * P_);
        }
    }

    // Epilogue: direct float2 stores from fragments (sector-aligned)
    #pragma unroll
    for (int mt = 0; mt < 2; mt++)
        #pragma unroll
        for (int nt = 0; nt < 4; nt++) {
            int r = m0 + wm * 32 + mt * 16 + lr;
            int c = n0 + wn * 32 + nt * 8 + lc * 2;
            float2 v0 = { acc[mt][nt][0], acc[mt][nt][1] };
            float2 v1 = { acc[mt][nt][2], acc[mt][nt][3] };
            *reinterpret_cast<float2*>(Yb + (size_t)r * P_ + c)       = v0;
            *reinterpret_cast<float2*>(Yb + (size_t)(r + 8) * P_ + c) = v1;
        }
}

// ---------------------------------------------------------------------------
// Stage 3: multi-dilate window attention
// ---------------------------------------------------------------------------
__device__ __forceinline__ int reflect_i(int t, int n) {
    return t < 0 ? -t : (t >= n ? 2*n - 2 - t : t);
}

__global__ __launch_bounds__(256) void attn_kernel()
{
    int p    = blockIdx.x * 256 + threadIdx.x;
    int head = blockIdx.y & 1;
    int dil  = blockIdx.y >> 1;
    int b    = blockIdx.z;
    int dl   = dil + 1;

    int y  = p >> 7;
    int xx = p & 127;

    int nb[9];
    #pragma unroll
    for (int jy = 0; jy < 3; jy++) {
        int yy = reflect_i(y + (jy-1)*dl, H_);
        #pragma unroll
        for (int jx = 0; jx < 3; jx++) {
            int xc = reflect_i(xx + (jx-1)*dl, W_);
            nb[jy*3 + jx] = yy * W_ + xc;
        }
    }

    size_t chan0 = (size_t)b * MQKV + dil * C2 + head * HD;
    const float* qp = g_qkv + chan0 * P_;
    const float* kp = g_qkv + (chan0 + (size_t)C_)   * P_;
    const float* vp = g_qkv + (chan0 + (size_t)2*C_) * P_;

    float sc[9];
    #pragma unroll
    for (int j = 0; j < 9; j++) sc[j] = 0.f;

    #pragma unroll 4
    for (int d = 0; d < HD; d++) {
        float qd = qp[(size_t)d * P_ + p];
        const float* kr = kp + (size_t)d * P_;
        #pragma unroll
        for (int j = 0; j < 9; j++) sc[j] += qd * kr[nb[j]];
    }

    float mx = sc[0] * SCALE;
    #pragma unroll
    for (int j = 0; j < 9; j++) { sc[j] *= SCALE; mx = fmaxf(mx, sc[j]); }
    float sum = 0.f;
    #pragma unroll
    for (int j = 0; j < 9; j++) { sc[j] = __expf(sc[j] - mx); sum += sc[j]; }
    float inv = 1.f / sum;

    float* op = g_xo + ((size_t)b * C_ + dil * C2 + head * HD) * P_ + p;
    #pragma unroll 4
    for (int d = 0; d < HD; d++) {
        const float* vr = vp + (size_t)d * P_;
        float a = 0.f;
        #pragma unroll
        for (int j = 0; j < 9; j++) a += sc[j] * vr[nb[j]];
        op[(size_t)d * P_] = a * inv;
    }
}

// ---------------------------------------------------------------------------
extern "C" void kernel_launch(void* const* d_in, const int* in_sizes, int n_in,
                              void* d_out, int out_size)
{
    const float* x      = (const float*)d_in[0];
    const float* pos_w  = (const float*)d_in[1];
    const float* pos_b  = (const float*)d_in[2];
    const float* qkv_w  = (const float*)d_in[3];
    const float* proj_w = (const float*)d_in[4];
    float* out = (float*)d_out;

    float *gx, *gq, *go;
    cudaGetSymbolAddress((void**)&gx, g_x);
    cudaGetSymbolAddress((void**)&gq, g_qkv);
    cudaGetSymbolAddress((void**)&go, g_xo);

    // Stage 1: positional dwconv + residual + bias
    {
        int total = B_*C_*P_;
        pos_kernel<<<(total + 255)/256, 256>>>(x, pos_w, pos_b);
    }
    // Stage 2: qkv 1x1 conv (576 x 192 x 16384 per batch)
    {
        dim3 grid(P_/GBN, MQKV/GBM, B_);
        gemm_mma<<<grid, 256>>>(qkv_w, gx, gq, MQKV);
    }
    // Stage 3: attention
    {
        dim3 grid(P_/256, NH*ND, B_);
        attn_kernel<<<grid, 256>>>();
    }
    // Stage 4: projection (192 x 192 x 16384 per batch)
    {
        dim3 grid(P_/GBN, C_/GBM, B_);
        gemm_mma<<<grid, 256>>>(proj_w, go, out, C_);
    }
}